// round 12
// baseline (speedup 1.0000x reference)
#include <cuda_runtime.h>
#include <cuda_bf16.h>
#include <math.h>
#include <stdint.h>

// Problem constants
#define Bsz 2
#define Sq  2048
#define Dm  1024
#define Hn  16
#define HDm 64

// ---------------------------------------------------------------------------
// Scratch (__device__ globals; allocation-free rule)
// ---------------------------------------------------------------------------
#define HEADELEMS ((size_t)Bsz * Hn * Sq * HDm)
__device__ __nv_bfloat16 g_q_hi[HEADELEMS];
__device__ __nv_bfloat16 g_q_lo[HEADELEMS];
__device__ __nv_bfloat16 g_k_hi[HEADELEMS];
__device__ __nv_bfloat16 g_k_lo[HEADELEMS];
__device__ __nv_bfloat16 g_v_hi[HEADELEMS];
__device__ __nv_bfloat16 g_v_lo[HEADELEMS];
__device__ __nv_bfloat16 g_att_hi[HEADELEMS];     // raw-reshape layout
__device__ __nv_bfloat16 g_att_lo[HEADELEMS];
__device__ __nv_bfloat16 g_x_hi[(size_t)Bsz * Sq * Dm];
__device__ __nv_bfloat16 g_x_lo[(size_t)Bsz * Sq * Dm];
__device__ __nv_bfloat16 g_wq_hi[(size_t)3 * Dm * Dm];   // W_qkv^T [3072][1024]
__device__ __nv_bfloat16 g_wq_lo[(size_t)3 * Dm * Dm];
__device__ __nv_bfloat16 g_wo_hi[(size_t)Dm * Dm];       // W_out^T [1024][1024]
__device__ __nv_bfloat16 g_wo_lo[(size_t)Dm * Dm];

// ---------------------------------------------------------------------------
// Baseline-PTX helpers
// ---------------------------------------------------------------------------
__device__ __forceinline__ uint32_t smem_u32(const void* p) {
    uint32_t a;
    asm("{ .reg .u64 t; cvta.to.shared.u64 t, %1; cvt.u32.u64 %0, t; }" : "=r"(a) : "l"(p));
    return a;
}
__device__ __forceinline__ void cp_async16(uint32_t s, const void* g) {
    asm volatile("cp.async.cg.shared.global [%0], [%1], 16;\n" :: "r"(s), "l"(g));
}
__device__ __forceinline__ void cp_commit() {
    asm volatile("cp.async.commit_group;\n" ::: "memory");
}
__device__ __forceinline__ void cp_wait0() {
    asm volatile("cp.async.wait_group 0;\n" ::: "memory");
}
__device__ __forceinline__ void cp_wait1() {
    asm volatile("cp.async.wait_group 1;\n" ::: "memory");
}
__device__ __forceinline__ void ldm_x4(uint32_t* r, uint32_t addr) {
    asm volatile("ldmatrix.sync.aligned.m8n8.x4.shared.b16 {%0,%1,%2,%3}, [%4];"
                 : "=r"(r[0]), "=r"(r[1]), "=r"(r[2]), "=r"(r[3]) : "r"(addr));
}
__device__ __forceinline__ void ldm_x4_t(uint32_t* r, uint32_t addr) {
    asm volatile("ldmatrix.sync.aligned.m8n8.x4.trans.shared.b16 {%0,%1,%2,%3}, [%4];"
                 : "=r"(r[0]), "=r"(r[1]), "=r"(r[2]), "=r"(r[3]) : "r"(addr));
}
__device__ __forceinline__ void mma16816(float* d, const uint32_t* a,
                                         uint32_t b0, uint32_t b1) {
    asm volatile(
        "mma.sync.aligned.m16n8k16.row.col.f32.bf16.bf16.f32 "
        "{%0,%1,%2,%3},{%4,%5,%6,%7},{%8,%9},{%0,%1,%2,%3};"
        : "+f"(d[0]), "+f"(d[1]), "+f"(d[2]), "+f"(d[3])
        : "r"(a[0]), "r"(a[1]), "r"(a[2]), "r"(a[3]), "r"(b0), "r"(b1));
}
__device__ __forceinline__ uint32_t pack_bf2(float a, float b) {
    __nv_bfloat162 h = __floats2bfloat162_rn(a, b);
    return *(uint32_t*)&h;
}

// ---------------------------------------------------------------------------
// Conversion kernels
// ---------------------------------------------------------------------------
__global__ void split_ew(const float* __restrict__ A,
                         __nv_bfloat16* __restrict__ hi, __nv_bfloat16* __restrict__ lo)
{
    int i = blockIdx.x * blockDim.x + threadIdx.x;
    float4 v = ((const float4*)A)[i];
    __nv_bfloat16 h0 = __float2bfloat16(v.x), h1 = __float2bfloat16(v.y);
    __nv_bfloat16 h2 = __float2bfloat16(v.z), h3 = __float2bfloat16(v.w);
    __nv_bfloat162* H = (__nv_bfloat162*)hi;
    __nv_bfloat162* L = (__nv_bfloat162*)lo;
    H[2 * i]     = __nv_bfloat162(h0, h1);
    H[2 * i + 1] = __nv_bfloat162(h2, h3);
    L[2 * i]     = __nv_bfloat162(__float2bfloat16(v.x - __bfloat162float(h0)),
                                  __float2bfloat16(v.y - __bfloat162float(h1)));
    L[2 * i + 1] = __nv_bfloat162(__float2bfloat16(v.z - __bfloat162float(h2)),
                                  __float2bfloat16(v.w - __bfloat162float(h3)));
}

__global__ void transpose_split(const float* __restrict__ W, int K, int N,
                                __nv_bfloat16* __restrict__ Thi, __nv_bfloat16* __restrict__ Tlo)
{
    __shared__ float t[32][33];
    int n0 = blockIdx.x * 32, k0 = blockIdx.y * 32;
    int tx = threadIdx.x, ty = threadIdx.y;  // 32x8
#pragma unroll
    for (int r = ty; r < 32; r += 8)
        t[r][tx] = W[(size_t)(k0 + r) * N + n0 + tx];
    __syncthreads();
#pragma unroll
    for (int r = ty; r < 32; r += 8) {
        float v = t[tx][r];
        __nv_bfloat16 h = __float2bfloat16(v);
        size_t dst = (size_t)(n0 + r) * K + k0 + tx;
        Thi[dst] = h;
        Tlo[dst] = __float2bfloat16(v - __bfloat162float(h));
    }
}

// ---------------------------------------------------------------------------
// bf16x2-split GEMM via mma.sync (R9-proven): 256 threads, 8 warps (2m x 4n),
// warp tile 64x32, K-chunk 32, double-buffered, 2 CTAs/SM.
// ---------------------------------------------------------------------------
#define TILE_B   10240
#define GEMM_SMEM (2 * 4 * TILE_B)           // 81920

__global__ __launch_bounds__(256, 2) void gemm_mma(
    int M, int N, int K,
    const __nv_bfloat16* __restrict__ Ahi, const __nv_bfloat16* __restrict__ Alo,
    const __nv_bfloat16* __restrict__ Bhi, const __nv_bfloat16* __restrict__ Blo,
    const float* __restrict__ bias, float* __restrict__ C, int mode,
    __nv_bfloat16* __restrict__ qh, __nv_bfloat16* __restrict__ ql,
    __nv_bfloat16* __restrict__ kh, __nv_bfloat16* __restrict__ kl,
    __nv_bfloat16* __restrict__ vh, __nv_bfloat16* __restrict__ vl)
{
    extern __shared__ char smc[];
    const uint32_t sb = smem_u32(smc);
    const int tid  = threadIdx.x;
    const int wid  = tid >> 5;
    const int lane = tid & 31;
    const int by = blockIdx.y * 128;
    const int bx = blockIdx.x * 128;
    const int wm = wid & 1;
    const int wn = wid >> 1;

    auto tile = [&](int buf, int t) -> uint32_t {
        return sb + (uint32_t)(buf * 4 + t) * TILE_B;
    };
    auto load_tile = [&](uint32_t sbase, const __nv_bfloat16* src, int row0, int k0) {
#pragma unroll
        for (int g = tid; g < 512; g += 256) {
            int r = g >> 2, s = g & 3;
            cp_async16(sbase + (uint32_t)(r * 80 + s * 16),
                       (const char*)(src + (size_t)(row0 + r) * K + k0) + s * 16);
        }
    };
    auto load_chunk = [&](int buf, int k0) {
        load_tile(tile(buf, 0), Ahi, by, k0);
        load_tile(tile(buf, 1), Alo, by, k0);
        load_tile(tile(buf, 2), Bhi, bx, k0);
        load_tile(tile(buf, 3), Blo, bx, k0);
        cp_commit();
    };

    float acc[4][4][4];
#pragma unroll
    for (int i = 0; i < 4; i++)
#pragma unroll
        for (int j = 0; j < 4; j++)
#pragma unroll
            for (int k = 0; k < 4; k++) acc[i][j][k] = 0.f;

    const int NC = K / 32;
    load_chunk(0, 0);

    const uint32_t lrow = (uint32_t)(lane & 15);
    const uint32_t lkb  = (uint32_t)((lane >> 4) * 8) * 2;

    for (int c = 0; c < NC; c++) {
        const int cur = c & 1;
        if (c + 1 < NC) { load_chunk(cur ^ 1, (c + 1) * 32); cp_wait1(); }
        else            { cp_wait0(); }
        __syncthreads();

        const uint32_t sAh = tile(cur, 0), sAl = tile(cur, 1);
        const uint32_t sBh = tile(cur, 2), sBl = tile(cur, 3);

#pragma unroll
        for (int ks = 0; ks < 2; ks++) {
            const uint32_t kby = (uint32_t)(ks * 16) * 2 + lkb;
            uint32_t a[4][4], bh0[4], bh1[4], bl0[4], bl1[4];

#pragma unroll
            for (int mt = 0; mt < 4; mt++)
                ldm_x4(a[mt], sAh + (uint32_t)((wm * 64 + mt * 16) + lrow) * 80 + kby);
            ldm_x4(bh0, sBh + (uint32_t)(wn * 32 + lrow) * 80 + kby);
            ldm_x4(bh1, sBh + (uint32_t)(wn * 32 + 16 + lrow) * 80 + kby);
            ldm_x4(bl0, sBl + (uint32_t)(wn * 32 + lrow) * 80 + kby);
            ldm_x4(bl1, sBl + (uint32_t)(wn * 32 + 16 + lrow) * 80 + kby);

#pragma unroll
            for (int mt = 0; mt < 4; mt++) {
                mma16816(acc[mt][0], a[mt], bh0[0], bh0[2]);
                mma16816(acc[mt][1], a[mt], bh0[1], bh0[3]);
                mma16816(acc[mt][2], a[mt], bh1[0], bh1[2]);
                mma16816(acc[mt][3], a[mt], bh1[1], bh1[3]);
            }
#pragma unroll
            for (int mt = 0; mt < 4; mt++) {
                mma16816(acc[mt][0], a[mt], bl0[0], bl0[2]);
                mma16816(acc[mt][1], a[mt], bl0[1], bl0[3]);
                mma16816(acc[mt][2], a[mt], bl1[0], bl1[2]);
                mma16816(acc[mt][3], a[mt], bl1[1], bl1[3]);
            }
#pragma unroll
            for (int mt = 0; mt < 4; mt++)
                ldm_x4(a[mt], sAl + (uint32_t)((wm * 64 + mt * 16) + lrow) * 80 + kby);
#pragma unroll
            for (int mt = 0; mt < 4; mt++) {
                mma16816(acc[mt][0], a[mt], bh0[0], bh0[2]);
                mma16816(acc[mt][1], a[mt], bh0[1], bh0[3]);
                mma16816(acc[mt][2], a[mt], bh1[0], bh1[2]);
                mma16816(acc[mt][3], a[mt], bh1[1], bh1[3]);
            }
        }
        __syncthreads();
    }

    const int r0 = lane >> 2;
    const int c0 = (lane & 3) * 2;

    if (mode == 0) {
#pragma unroll
        for (int mt = 0; mt < 4; mt++) {
#pragma unroll
            for (int nt = 0; nt < 4; nt++) {
                int row = by + wm * 64 + mt * 16 + r0;
                int col = bx + wn * 32 + nt * 8 + c0;
                float b0 = bias[col], b1 = bias[col + 1];
                *(float2*)(C + (size_t)row * N + col) =
                    make_float2(acc[mt][nt][0] + b0, acc[mt][nt][1] + b1);
                *(float2*)(C + (size_t)(row + 8) * N + col) =
                    make_float2(acc[mt][nt][2] + b0, acc[mt][nt][3] + b1);
            }
        }
    } else {
        int col0 = bx + wn * 32;
        int h = col0 / 192;
        int t = (col0 % 192) / 64;
        int hdb = col0 & 63;
        __nv_bfloat16* dh = (t == 0) ? qh : (t == 1) ? kh : vh;
        __nv_bfloat16* dl = (t == 0) ? ql : (t == 1) ? kl : vl;
#pragma unroll
        for (int mt = 0; mt < 4; mt++) {
#pragma unroll
            for (int nt = 0; nt < 4; nt++) {
                int gr = by + wm * 64 + mt * 16 + r0;
                int bb = gr >> 11, s = gr & 2047;
                int hd = hdb + nt * 8 + c0;
                int col = col0 + nt * 8 + c0;
                float b0 = bias[col], b1 = bias[col + 1];
                size_t d0 = (((size_t)(bb * Hn + h)) * Sq + s) * HDm + hd;
                size_t d1 = d0 + 8 * HDm;
#pragma unroll
                for (int rr = 0; rr < 2; rr++) {
                    float v0 = acc[mt][nt][2 * rr + 0] + b0;
                    float v1 = acc[mt][nt][2 * rr + 1] + b1;
                    __nv_bfloat162 hh = __floats2bfloat162_rn(v0, v1);
                    __nv_bfloat162 ll = __floats2bfloat162_rn(
                        v0 - __bfloat162float(hh.x), v1 - __bfloat162float(hh.y));
                    size_t d = rr ? d1 : d0;
                    *(__nv_bfloat162*)(dh + d) = hh;
                    *(__nv_bfloat162*)(dl + d) = ll;
                }
            }
        }
    }
}

// ---------------------------------------------------------------------------
// Flash attention v2: CTA = 128 q rows, 4 warps, each warp owns 32 rows
// (2 bands of 16). K/V fragments reused across both bands -> 4.8 MMA/ldm.
// smem: Q hi/lo 128x72 + double-buffered K/V hi/lo 64x72 = 108KB; 2 CTAs/SM.
// ---------------------------------------------------------------------------
#define FKV  9216                     // 64 * 144
#define FQT  18432                    // 128 * 144
#define FLASH_SMEM (2 * FQT + 2 * 4 * FKV)   // 110592

__global__ __launch_bounds__(128) void flash_mma(
    const __nv_bfloat16* __restrict__ qh, const __nv_bfloat16* __restrict__ ql,
    const __nv_bfloat16* __restrict__ kh, const __nv_bfloat16* __restrict__ kl,
    const __nv_bfloat16* __restrict__ vh, const __nv_bfloat16* __restrict__ vl,
    __nv_bfloat16* __restrict__ ah, __nv_bfloat16* __restrict__ al)
{
    extern __shared__ char smc[];
    const uint32_t sb = smem_u32(smc);
    const int tid  = threadIdx.x;
    const int wid  = tid >> 5;
    const int lane = tid & 31;
    const int bh = blockIdx.y;
    const int qb = blockIdx.x;          // 128-row q block, 0..15

    const uint32_t sQh = sb, sQl = sb + FQT;
    auto kvtile = [&](int buf, int t) -> uint32_t {
        return sb + 2 * FQT + (uint32_t)(buf * 4 + t) * FKV;
    };

    const char* hb_q  = (const char*)(qh + (size_t)bh * Sq * HDm);
    const char* hb_ql = (const char*)(ql + (size_t)bh * Sq * HDm);
    const char* hb_k  = (const char*)(kh + (size_t)bh * Sq * HDm);
    const char* hb_kl = (const char*)(kl + (size_t)bh * Sq * HDm);
    const char* hb_v  = (const char*)(vh + (size_t)bh * Sq * HDm);
    const char* hb_vl = (const char*)(vl + (size_t)bh * Sq * HDm);

    auto load_q = [&](uint32_t dst, const char* srcbase, int row0) {
#pragma unroll
        for (int g = tid; g < 1024; g += 128) {
            int r = g >> 3, ch = g & 7;
            cp_async16(dst + (uint32_t)(r * 144 + ch * 16),
                       srcbase + (size_t)(row0 + r) * 128 + ch * 16);
        }
    };
    auto load_kvt = [&](uint32_t dst, const char* srcbase, int row0) {
#pragma unroll
        for (int g = tid; g < 512; g += 128) {
            int r = g >> 3, ch = g & 7;
            cp_async16(dst + (uint32_t)(r * 144 + ch * 16),
                       srcbase + (size_t)(row0 + r) * 128 + ch * 16);
        }
    };
    auto load_kv = [&](int buf, int jb) {
        load_kvt(kvtile(buf, 0), hb_k,  jb * 64);
        load_kvt(kvtile(buf, 1), hb_kl, jb * 64);
        load_kvt(kvtile(buf, 2), hb_v,  jb * 64);
        load_kvt(kvtile(buf, 3), hb_vl, jb * 64);
        cp_commit();
    };

    load_q(sQh, hb_q,  qb * 128);
    load_q(sQl, hb_ql, qb * 128);
    load_kv(0, 0);

    float o[2][8][4];
#pragma unroll
    for (int b2 = 0; b2 < 2; b2++)
#pragma unroll
        for (int t = 0; t < 8; t++)
#pragma unroll
            for (int j = 0; j < 4; j++) o[b2][t][j] = 0.f;
    float m[2][2], l[2][2];
#pragma unroll
    for (int b2 = 0; b2 < 2; b2++) { m[b2][0] = m[b2][1] = -1e30f; l[b2][0] = l[b2][1] = 0.f; }

    const uint32_t lrow = (uint32_t)(lane & 15);
    const uint32_t lkb  = (uint32_t)((lane >> 4) * 16);
    // per-band Q row offset in smem
    uint32_t qoffb[2];
    qoffb[0] = (uint32_t)(wid * 32 + (lane & 15)) * 144 + lkb;
    qoffb[1] = (uint32_t)(wid * 32 + 16 + (lane & 15)) * 144 + lkb;
    const int rloc = lane >> 2;           // row within 8-row group
    const int cpair = (lane & 3) * 2;
    const float scale = 0.125f;
    const int rowbase = qb * 128 + wid * 32;   // warp's first global q row

    const int NB = 2 * qb + 2;            // kv blocks 0..2qb+1
    for (int jb = 0; jb < NB; jb++) {
        const int buf = jb & 1;
        if (jb + 1 < NB) { load_kv(buf ^ 1, jb + 1); cp_wait1(); }
        else             { cp_wait0(); }
        __syncthreads();

        const uint32_t sKh = kvtile(buf, 0), sKl = kvtile(buf, 1);
        const uint32_t sVh = kvtile(buf, 2), sVl = kvtile(buf, 3);

        // ----- S = Q @ K^T (3-pass hi/lo), 2 bands share K fragments -----
        float s[2][8][4];
#pragma unroll
        for (int b2 = 0; b2 < 2; b2++)
#pragma unroll
            for (int t = 0; t < 8; t++)
#pragma unroll
                for (int j = 0; j < 4; j++) s[b2][t][j] = 0.f;

#pragma unroll
        for (int kc = 0; kc < 4; kc++) {
            const uint32_t kof = (uint32_t)(kc * 32);
            uint32_t aq[2][4], aq2[2][4], b[4][4];
#pragma unroll
            for (int b2 = 0; b2 < 2; b2++) {
                ldm_x4(aq[b2],  sQh + qoffb[b2] + kof);
                ldm_x4(aq2[b2], sQl + qoffb[b2] + kof);
            }
#pragma unroll
            for (int g = 0; g < 4; g++)
                ldm_x4(b[g], sKh + (uint32_t)(g * 16 + (int)lrow) * 144 + lkb + kof);
#pragma unroll
            for (int b2 = 0; b2 < 2; b2++)
#pragma unroll
                for (int g = 0; g < 4; g++) {
                    mma16816(s[b2][2 * g + 0], aq[b2],  b[g][0], b[g][2]);
                    mma16816(s[b2][2 * g + 1], aq[b2],  b[g][1], b[g][3]);
                    mma16816(s[b2][2 * g + 0], aq2[b2], b[g][0], b[g][2]);
                    mma16816(s[b2][2 * g + 1], aq2[b2], b[g][1], b[g][3]);
                }
#pragma unroll
            for (int g = 0; g < 4; g++)
                ldm_x4(b[g], sKl + (uint32_t)(g * 16 + (int)lrow) * 144 + lkb + kof);
#pragma unroll
            for (int b2 = 0; b2 < 2; b2++)
#pragma unroll
                for (int g = 0; g < 4; g++) {
                    mma16816(s[b2][2 * g + 0], aq[b2], b[g][0], b[g][2]);
                    mma16816(s[b2][2 * g + 1], aq[b2], b[g][1], b[g][3]);
                }
        }

        // scale + causal mask (global-index compare on straddling blocks)
        if (jb >= 2 * qb) {
#pragma unroll
            for (int b2 = 0; b2 < 2; b2++)
#pragma unroll
                for (int t = 0; t < 8; t++)
#pragma unroll
                    for (int j = 0; j < 4; j++) {
                        int gcol = jb * 64 + 8 * t + cpair + (j & 1);
                        int grow = rowbase + b2 * 16 + rloc + (j >> 1) * 8;
                        s[b2][t][j] = (gcol > grow) ? -1e30f : s[b2][t][j] * scale;
                    }
        } else {
#pragma unroll
            for (int b2 = 0; b2 < 2; b2++)
#pragma unroll
                for (int t = 0; t < 8; t++)
#pragma unroll
                    for (int j = 0; j < 4; j++) s[b2][t][j] *= scale;
        }

        // ----- online softmax per band -----
        uint32_t ph[2][8][2], pl[2][8][2];
#pragma unroll
        for (int b2 = 0; b2 < 2; b2++) {
            float rm0 = -1e30f, rm1 = -1e30f;
#pragma unroll
            for (int t = 0; t < 8; t++) {
                rm0 = fmaxf(rm0, fmaxf(s[b2][t][0], s[b2][t][1]));
                rm1 = fmaxf(rm1, fmaxf(s[b2][t][2], s[b2][t][3]));
            }
            rm0 = fmaxf(rm0, __shfl_xor_sync(0xffffffffu, rm0, 1, 4));
            rm0 = fmaxf(rm0, __shfl_xor_sync(0xffffffffu, rm0, 2, 4));
            rm1 = fmaxf(rm1, __shfl_xor_sync(0xffffffffu, rm1, 1, 4));
            rm1 = fmaxf(rm1, __shfl_xor_sync(0xffffffffu, rm1, 2, 4));

            float mn0 = fmaxf(m[b2][0], rm0), mn1 = fmaxf(m[b2][1], rm1);
            float corr0 = __expf(m[b2][0] - mn0), corr1 = __expf(m[b2][1] - mn1);
            m[b2][0] = mn0; m[b2][1] = mn1;

            float rs0 = 0.f, rs1 = 0.f;
#pragma unroll
            for (int t = 0; t < 8; t++) {
                s[b2][t][0] = __expf(s[b2][t][0] - mn0); rs0 += s[b2][t][0];
                s[b2][t][1] = __expf(s[b2][t][1] - mn0); rs0 += s[b2][t][1];
                s[b2][t][2] = __expf(s[b2][t][2] - mn1); rs1 += s[b2][t][2];
                s[b2][t][3] = __expf(s[b2][t][3] - mn1); rs1 += s[b2][t][3];
            }
            rs0 += __shfl_xor_sync(0xffffffffu, rs0, 1, 4);
            rs0 += __shfl_xor_sync(0xffffffffu, rs0, 2, 4);
            rs1 += __shfl_xor_sync(0xffffffffu, rs1, 1, 4);
            rs1 += __shfl_xor_sync(0xffffffffu, rs1, 2, 4);
            l[b2][0] = l[b2][0] * corr0 + rs0;
            l[b2][1] = l[b2][1] * corr1 + rs1;
#pragma unroll
            for (int t = 0; t < 8; t++) {
                o[b2][t][0] *= corr0; o[b2][t][1] *= corr0;
                o[b2][t][2] *= corr1; o[b2][t][3] *= corr1;
            }
            // P -> bf16 hi/lo A-fragments
#pragma unroll
            for (int t = 0; t < 8; t++) {
                __nv_bfloat162 h0 = __floats2bfloat162_rn(s[b2][t][0], s[b2][t][1]);
                __nv_bfloat162 h1 = __floats2bfloat162_rn(s[b2][t][2], s[b2][t][3]);
                ph[b2][t][0] = *(uint32_t*)&h0;
                ph[b2][t][1] = *(uint32_t*)&h1;
                pl[b2][t][0] = pack_bf2(s[b2][t][0] - __bfloat162float(h0.x),
                                        s[b2][t][1] - __bfloat162float(h0.y));
                pl[b2][t][1] = pack_bf2(s[b2][t][2] - __bfloat162float(h1.x),
                                        s[b2][t][3] - __bfloat162float(h1.y));
            }
        }

        // ----- O += P @ V (3-pass), 2 bands share V fragments -----
        const uint32_t vrow = (uint32_t)(lane & 15) * 144;
        const uint32_t vhd  = (uint32_t)((lane >> 4) * 8) * 2;
#pragma unroll
        for (int kc = 0; kc < 4; kc++) {
            uint32_t a[2][4], a2[2][4];
#pragma unroll
            for (int b2 = 0; b2 < 2; b2++) {
                a[b2][0] = ph[b2][2 * kc][0]; a[b2][1] = ph[b2][2 * kc][1];
                a[b2][2] = ph[b2][2 * kc + 1][0]; a[b2][3] = ph[b2][2 * kc + 1][1];
                a2[b2][0] = pl[b2][2 * kc][0]; a2[b2][1] = pl[b2][2 * kc][1];
                a2[b2][2] = pl[b2][2 * kc + 1][0]; a2[b2][3] = pl[b2][2 * kc + 1][1];
            }
            const uint32_t rb = (uint32_t)(kc * 16) * 144;
#pragma unroll
            for (int hg = 0; hg < 4; hg++) {
                uint32_t bv[4];
                ldm_x4_t(bv, sVh + rb + vrow + (uint32_t)(hg * 16) * 2 + vhd);
#pragma unroll
                for (int b2 = 0; b2 < 2; b2++) {
                    mma16816(o[b2][2 * hg + 0], a[b2],  bv[0], bv[1]);
                    mma16816(o[b2][2 * hg + 1], a[b2],  bv[2], bv[3]);
                    mma16816(o[b2][2 * hg + 0], a2[b2], bv[0], bv[1]);
                    mma16816(o[b2][2 * hg + 1], a2[b2], bv[2], bv[3]);
                }
                ldm_x4_t(bv, sVl + rb + vrow + (uint32_t)(hg * 16) * 2 + vhd);
#pragma unroll
                for (int b2 = 0; b2 < 2; b2++) {
                    mma16816(o[b2][2 * hg + 0], a[b2], bv[0], bv[1]);
                    mma16816(o[b2][2 * hg + 1], a[b2], bv[2], bv[3]);
                }
            }
        }
        __syncthreads();
    }

    // ----- epilogue -----
#pragma unroll
    for (int b2 = 0; b2 < 2; b2++) {
        const float inv0 = 1.0f / l[b2][0], inv1 = 1.0f / l[b2][1];
        const size_t rb0 = ((size_t)bh * Sq + (size_t)(rowbase + b2 * 16 + rloc)) * HDm;
        const size_t rb1 = rb0 + 8 * HDm;
#pragma unroll
        for (int t = 0; t < 8; t++) {
            int hd = 8 * t + cpair;
            float v0 = o[b2][t][0] * inv0, v1 = o[b2][t][1] * inv0;
            float v2 = o[b2][t][2] * inv1, v3 = o[b2][t][3] * inv1;
            __nv_bfloat162 h0 = __floats2bfloat162_rn(v0, v1);
            __nv_bfloat162 h1 = __floats2bfloat162_rn(v2, v3);
            *(__nv_bfloat162*)(ah + rb0 + hd) = h0;
            *(__nv_bfloat162*)(ah + rb1 + hd) = h1;
            *(__nv_bfloat162*)(al + rb0 + hd) = __floats2bfloat162_rn(
                v0 - __bfloat162float(h0.x), v1 - __bfloat162float(h0.y));
            *(__nv_bfloat162*)(al + rb1 + hd) = __floats2bfloat162_rn(
                v2 - __bfloat162float(h1.x), v3 - __bfloat162float(h1.y));
        }
    }
}

// ---------------------------------------------------------------------------
extern "C" void kernel_launch(void* const* d_in, const int* in_sizes, int n_in,
                              void* d_out, int out_size)
{
    (void)in_sizes; (void)n_in; (void)out_size;
    const float* x    = (const float*)d_in[0];
    const float* Wqkv = (const float*)d_in[1];
    const float* bqkv = (const float*)d_in[2];
    const float* Wout = (const float*)d_in[3];
    const float* bout = (const float*)d_in[4];
    float* out = (float*)d_out;

    __nv_bfloat16 *xh, *xl, *wqh, *wql, *woh, *wol;
    __nv_bfloat16 *qh, *ql, *kh, *kl, *vh, *vl, *ath, *atl;
    cudaGetSymbolAddress((void**)&xh, g_x_hi);
    cudaGetSymbolAddress((void**)&xl, g_x_lo);
    cudaGetSymbolAddress((void**)&wqh, g_wq_hi);
    cudaGetSymbolAddress((void**)&wql, g_wq_lo);
    cudaGetSymbolAddress((void**)&woh, g_wo_hi);
    cudaGetSymbolAddress((void**)&wol, g_wo_lo);
    cudaGetSymbolAddress((void**)&qh, g_q_hi);
    cudaGetSymbolAddress((void**)&ql, g_q_lo);
    cudaGetSymbolAddress((void**)&kh, g_k_hi);
    cudaGetSymbolAddress((void**)&kl, g_k_lo);
    cudaGetSymbolAddress((void**)&vh, g_v_hi);
    cudaGetSymbolAddress((void**)&vl, g_v_lo);
    cudaGetSymbolAddress((void**)&ath, g_att_hi);
    cudaGetSymbolAddress((void**)&atl, g_att_lo);

    split_ew<<<(Bsz * Sq * Dm / 4) / 256, 256>>>(x, xh, xl);
    transpose_split<<<dim3(3 * Dm / 32, Dm / 32), dim3(32, 8)>>>(Wqkv, Dm, 3 * Dm, wqh, wql);
    transpose_split<<<dim3(Dm / 32, Dm / 32), dim3(32, 8)>>>(Wout, Dm, Dm, woh, wol);

    cudaFuncSetAttribute(gemm_mma, cudaFuncAttributeMaxDynamicSharedMemorySize, GEMM_SMEM);
    cudaFuncSetAttribute(flash_mma, cudaFuncAttributeMaxDynamicSharedMemorySize, FLASH_SMEM);

    // 1) QKV projection, scatter head-major bf16 hi/lo Q/K/V
    gemm_mma<<<dim3(3 * Dm / 128, Bsz * Sq / 128), 256, GEMM_SMEM>>>(
        Bsz * Sq, 3 * Dm, Dm, xh, xl, wqh, wql, bqkv, nullptr, 1,
        qh, ql, kh, kl, vh, vl);

    // 2) causal flash attention v2 (128-row q tiles)
    flash_mma<<<dim3(Sq / 128, Bsz * Hn), 128, FLASH_SMEM>>>(
        qh, ql, kh, kl, vh, vl, ath, atl);

    // 3) output projection on raw-reshaped values
    gemm_mma<<<dim3(Dm / 128, Bsz * Sq / 128), 256, GEMM_SMEM>>>(
        Bsz * Sq, Dm, Dm, ath, atl, woh, wol, bout, out, 0,
        nullptr, nullptr, nullptr, nullptr, nullptr, nullptr);
}